// round 8
// baseline (speedup 1.0000x reference)
#include <cuda_runtime.h>
#include <cuda_fp16.h>
#include <cstdint>

#define TPB     256
#define TILE_M  64
#define STATE   24
#define L1D     100
#define L2D     100
#define NHEAD   27
#define ACT     6

#define NT12    13
#define NT3     4
#define KS1     2
#define KS23    7

#define S1_32   36
#define LO1     16
#define S2_32   116
#define LO2     56

// ---- smem layout (b32 word offsets) ----
#define F_BP1   0
#define F_BP2   (F_BP1 + KS1*NT12*32*4)         //  3328
#define F_BP3   (F_BP2 + KS23*NT12*32*4)        // 14976
#define F_AS1   (F_BP3 + KS23*NT3*32*4)         // 18560
#define F_AS2   (F_AS1 + TILE_M*S1_32)          // 20864
#define F_TOTAL (F_AS2 + TILE_M*S2_32)          // 28288 words = 113152 B

__constant__ int c_pos[21]   = {0,6,7,12,13,14,18,19,20,21,24,25,26,27,28,30,31,32,33,34,35};
__constant__ int c_upper[15] = {1,2,3,4,5,8,9,10,11,15,16,17,22,23,29};

__device__ __forceinline__ uint32_t packh(__half a, __half b) {
    return (uint32_t)__half_as_ushort(a) | ((uint32_t)__half_as_ushort(b) << 16);
}
__device__ __forceinline__ void split2(float v0, float v1, uint32_t& hi, uint32_t& lo) {
    __half h0 = __float2half_rn(v0), h1 = __float2half_rn(v1);
    __half l0 = __float2half_rn(v0 - __half2float(h0));
    __half l1 = __float2half_rn(v1 - __half2float(h1));
    hi = packh(h0, h1); lo = packh(l0, l1);
}

__device__ __forceinline__ void mma16(float* c, const uint32_t* a, uint32_t b0, uint32_t b1) {
    asm volatile("mma.sync.aligned.m16n8k16.row.col.f32.f16.f16.f32 "
                 "{%0,%1,%2,%3},{%4,%5,%6,%7},{%8,%9},{%0,%1,%2,%3};"
                 : "+f"(c[0]), "+f"(c[1]), "+f"(c[2]), "+f"(c[3])
                 : "r"(a[0]), "r"(a[1]), "r"(a[2]), "r"(a[3]), "r"(b0), "r"(b1));
}

extern __shared__ uint32_t smem[];

// 3-term f16 warp GEMM (R5/R7-proven structure)
template<int KS, int MT, int NTW>
__device__ __forceinline__ void wgemm16(const uint32_t* __restrict__ A32, int S32, int LO,
                                        const uint4* __restrict__ Bp,
                                        int NTT, int nt0, int cnt,
                                        int wrow, int g, int t, int lane,
                                        float (&c)[MT][NTW][4])
{
    #pragma unroll
    for (int mt = 0; mt < MT; mt++)
        #pragma unroll
        for (int j = 0; j < NTW; j++)
            #pragma unroll
            for (int i = 0; i < 4; i++) c[mt][j][i] = 0.0f;

    #pragma unroll 1
    for (int ks = 0; ks < KS; ks++) {
        const int kb = ks * 8 + t;

        uint4 bfr[NTW];
        #pragma unroll
        for (int j = 0; j < NTW; j++)
            if (j < cnt) bfr[j] = Bp[(ks * NTT + nt0 + j) * 32 + lane];

        uint32_t ah[MT][4], al[MT][4];
        #pragma unroll
        for (int mt = 0; mt < MT; mt++) {
            const uint32_t* r0 = A32 + (wrow + 16 * mt + g) * S32;
            const uint32_t* r1 = r0 + 8 * S32;
            ah[mt][0] = r0[kb];          ah[mt][1] = r1[kb];
            ah[mt][2] = r0[kb + 4];      ah[mt][3] = r1[kb + 4];
            al[mt][0] = r0[kb + LO];     al[mt][1] = r1[kb + LO];
            al[mt][2] = r0[kb + LO + 4]; al[mt][3] = r1[kb + LO + 4];
        }

        #pragma unroll
        for (int term = 0; term < 3; term++)
            #pragma unroll
            for (int j = 0; j < NTW; j++) {
                if (j >= cnt) continue;
                uint32_t b0 = (term == 2) ? bfr[j].z : bfr[j].x;
                uint32_t b1 = (term == 2) ? bfr[j].w : bfr[j].y;
                #pragma unroll
                for (int mt = 0; mt < MT; mt++)
                    mma16(c[mt][j], (term == 1) ? al[mt] : ah[mt], b0, b1);
            }
    }
}

template<int MT, int NTW>
__device__ __forceinline__ void epi_relu16(float (&c)[MT][NTW][4], uint32_t* A2,
                                           int wrow, int nt0, int cnt, int g, int t)
{
    #pragma unroll
    for (int mt = 0; mt < MT; mt++) {
        const int row = wrow + 16 * mt + g;
        #pragma unroll
        for (int j = 0; j < NTW; j++) {
            if (j >= cnt) continue;
            const int nt = nt0 + j;
            if (nt == 12 && t >= 2) continue;      // cols >= 100
            const int pi = 4 * nt + t;
            uint32_t h, l;
            split2(fmaxf(c[mt][j][0], 0.f), fmaxf(c[mt][j][1], 0.f), h, l);
            A2[row * S2_32 + pi] = h;  A2[row * S2_32 + LO2 + pi] = l;
            split2(fmaxf(c[mt][j][2], 0.f), fmaxf(c[mt][j][3], 0.f), h, l);
            A2[(row + 8) * S2_32 + pi] = h;  A2[(row + 8) * S2_32 + LO2 + pi] = l;
        }
    }
}

__global__ void __launch_bounds__(TPB, 2)
actor_mma(const float* __restrict__ states,
          const float* __restrict__ W1, const float* __restrict__ b1,
          const float* __restrict__ W2, const float* __restrict__ b2,
          const float* __restrict__ Wm, const float* __restrict__ bm,
          const float* __restrict__ Wc, const float* __restrict__ bc,
          float* __restrict__ out, int B)
{
    const int tid  = threadIdx.x;
    const int lane = tid & 31;
    const int wid  = tid >> 5;
    const int g    = lane >> 2;
    const int t    = lane & 3;

    // layers 1,2 (M=64): M2 x N4
    const int wrow = (wid & 1) * 32;
    const int nh   = wid >> 1;
    const int nt0  = (nh == 0) ? 0 : (1 + 3 * nh);   // {0,4,7,10}
    const int ncnt = (nh == 0) ? 4 : 3;
    // head (M=64, N=32): M4 x N2
    const int wrow3 = (wid & 3) * 16;
    const int nt03  = (wid >> 2) * 2;

    uint32_t* As1 = smem + F_AS1;
    uint32_t* As2 = smem + F_AS2;
    const uint4* Bp1 = reinterpret_cast<const uint4*>(smem + F_BP1);
    const uint4* Bp2 = reinterpret_cast<const uint4*>(smem + F_BP2);
    const uint4* Bp3 = reinterpret_cast<const uint4*>(smem + F_BP3);

    // ---- stage packed f16 hi/lo weight fragments (biases folded as K-column) ----
    for (int i = tid; i < KS1 * NT12 * 32; i += TPB) {
        int ln = i & 31, slot = i >> 5, ks = slot / NT12, nt = slot - ks * NT12;
        int n = (ln >> 2) + 8 * nt, k0 = 16 * ks + 2 * (ln & 3);
        float w[4];
        #pragma unroll
        for (int q = 0; q < 4; q++) {
            int k = k0 + (q >> 1) * 8 + (q & 1);
            w[q] = (n < L1D) ? (k < STATE ? W1[n * STATE + k] : (k == STATE ? b1[n] : 0.f)) : 0.f;
        }
        uint4 fr; uint32_t lo0, lo1;
        split2(w[0], w[1], fr.x, lo0); split2(w[2], w[3], fr.y, lo1);
        fr.z = lo0; fr.w = lo1;
        reinterpret_cast<uint4*>(smem + F_BP1)[i] = fr;
    }
    for (int i = tid; i < KS23 * NT12 * 32; i += TPB) {
        int ln = i & 31, slot = i >> 5, ks = slot / NT12, nt = slot - ks * NT12;
        int n = (ln >> 2) + 8 * nt, k0 = 16 * ks + 2 * (ln & 3);
        float w[4];
        #pragma unroll
        for (int q = 0; q < 4; q++) {
            int k = k0 + (q >> 1) * 8 + (q & 1);
            w[q] = (n < L2D) ? (k < L1D ? W2[n * L1D + k] : (k == L1D ? b2[n] : 0.f)) : 0.f;
        }
        uint4 fr; uint32_t lo0, lo1;
        split2(w[0], w[1], fr.x, lo0); split2(w[2], w[3], fr.y, lo1);
        fr.z = lo0; fr.w = lo1;
        reinterpret_cast<uint4*>(smem + F_BP2)[i] = fr;
    }
    for (int i = tid; i < KS23 * NT3 * 32; i += TPB) {
        int ln = i & 31, slot = i >> 5, ks = slot / NT3, nt = slot - ks * NT3;
        int n = (ln >> 2) + 8 * nt, k0 = 16 * ks + 2 * (ln & 3);
        float w[4];
        #pragma unroll
        for (int q = 0; q < 4; q++) {
            int k = k0 + (q >> 1) * 8 + (q & 1);
            float v = 0.f;
            if (n < ACT)        v = k < L2D ? Wm[n * L2D + k] : (k == L2D ? bm[n] : 0.f);
            else if (n < NHEAD) v = k < L2D ? Wc[(n - ACT) * L2D + k] : (k == L2D ? bc[n - ACT] : 0.f);
            w[q] = v;
        }
        uint4 fr; uint32_t lo0, lo1;
        split2(w[0], w[1], fr.x, lo0); split2(w[2], w[3], fr.y, lo1);
        fr.z = lo0; fr.w = lo1;
        reinterpret_cast<uint4*>(smem + F_BP3)[i] = fr;
    }
    // one-time activation pad init:
    // As2: zero all, then persistent bias pair 50 (col 100)
    for (int i = tid; i < TILE_M * S2_32; i += TPB) As2[i] = 0u;
    __syncthreads();
    if (tid < TILE_M) {
        As2[tid * S2_32 + 50] = packh(__float2half_rn(1.f), __ushort_as_half(0));
        // As1 pads: pair 12 = bias col 24 (1,0); pairs 13..15 = 0 (hi+lo)
        uint32_t* rr = As1 + tid * S1_32;
        rr[12] = packh(__float2half_rn(1.f), __ushort_as_half(0));
        rr[LO1 + 12] = 0u;
        #pragma unroll
        for (int p = 13; p < 16; p++) { rr[p] = 0u; rr[LO1 + p] = 0u; }
    }
    __syncthreads();

    const int ntiles = (B + TILE_M - 1) / TILE_M;
    const int grid = gridDim.x;

    // ---- prefetch first tile's X (2 threads per row, 3 float4 each) ----
    float4 px0, px1, px2;
    if (tid < 2 * TILE_M && blockIdx.x < ntiles) {
        long m = (long)blockIdx.x * TILE_M + (tid >> 1); if (m >= B) m = B - 1;
        const float4* src = reinterpret_cast<const float4*>(states + m * STATE) + (tid & 1) * 3;
        px0 = src[0]; px1 = src[1]; px2 = src[2];
    }

    for (int tile = blockIdx.x; tile < ntiles; tile += grid) {
        // ---- write prefetched X into As1 hi/lo planes ----
        if (tid < 2 * TILE_M) {
            const int row = tid >> 1, half = tid & 1;
            uint32_t* rh = As1 + row * S1_32 + half * 6;
            uint32_t h, l;
            split2(px0.x, px0.y, h, l); rh[0] = h; rh[LO1 + 0] = l;
            split2(px0.z, px0.w, h, l); rh[1] = h; rh[LO1 + 1] = l;
            split2(px1.x, px1.y, h, l); rh[2] = h; rh[LO1 + 2] = l;
            split2(px1.z, px1.w, h, l); rh[3] = h; rh[LO1 + 3] = l;
            split2(px2.x, px2.y, h, l); rh[4] = h; rh[LO1 + 4] = l;
            split2(px2.z, px2.w, h, l); rh[5] = h; rh[LO1 + 5] = l;
        }
        // ---- prefetch next tile's X ----
        {
            int nxt = tile + grid;
            if (tid < 2 * TILE_M && nxt < ntiles) {
                long m = (long)nxt * TILE_M + (tid >> 1); if (m >= B) m = B - 1;
                const float4* src = reinterpret_cast<const float4*>(states + m * STATE) + (tid & 1) * 3;
                px0 = src[0]; px1 = src[1]; px2 = src[2];
            }
        }
        __syncthreads();                                   // S1: X ready

        // ---- layer 1: As1 -> As2 ----
        {
            float c1[2][4][4];
            wgemm16<KS1, 2, 4>(As1, S1_32, LO1, Bp1, NT12, nt0, ncnt, wrow, g, t, lane, c1);
            epi_relu16<2, 4>(c1, As2, wrow, nt0, ncnt, g, t);
        }
        __syncthreads();                                   // S2: hidden1 ready

        // ---- layer 2: As2 -> As2 (named barrier per m-group for anti-dep) ----
        {
            float c2[2][4][4];
            wgemm16<KS23, 2, 4>(As2, S2_32, LO2, Bp2, NT12, nt0, ncnt, wrow, g, t, lane, c2);
            asm volatile("bar.sync %0, %1;" :: "r"(1 + (wid & 1)), "r"(128) : "memory");
            epi_relu16<2, 4>(c2, As2, wrow, nt0, ncnt, g, t);
        }
        __syncthreads();                                   // S4: hidden2 ready

        // ---- head gemm + direct GMEM epilogue (no staging, no barrier) ----
        {
            float c3[1][2][4];
            wgemm16<KS23, 1, 2>(As2, S2_32, LO2, Bp3, NT3, nt03, 2, wrow3, g, t, lane, c3);
            const long mbase = (long)tile * TILE_M;
            float* outc = out + (size_t)B * ACT;
            #pragma unroll
            for (int j = 0; j < 2; j++)
                #pragma unroll
                for (int i = 0; i < 4; i++) {
                    int row = wrow3 + g + ((i >= 2) ? 8 : 0);
                    int col = 8 * (nt03 + j) + 2 * t + (i & 1);
                    long m = mbase + row;
                    float v = c3[0][j][i];
                    if (m < B) {
                        if (col < ACT) {
                            out[m * ACT + col] = tanhf(v);
                        } else if (col < NHEAD) {
                            float sp = fmaxf(v, 0.f) + log1pf(expf(-fabsf(v)));
                            outc[m * 36 + c_pos[col - ACT]] = sp;
                        }
                    }
                }
            // upper-triangle zeros (out is poisoned)
            if (tid < TILE_M) {
                long m = mbase + tid;
                if (m < B) {
                    #pragma unroll
                    for (int j = 0; j < 15; j++) outc[m * 36 + c_upper[j]] = 0.0f;
                }
            }
        }
        // no trailing barrier: As1 X-writes (next iter) touch pairs 0..11 only,
        // last read of As1 was layer 1 (pre-S2); As2 reads by head gemm complete
        // before next S1 in each warp's program order, and S1 orders all warps.
    }
}

extern "C" void kernel_launch(void* const* d_in, const int* in_sizes, int n_in,
                              void* d_out, int out_size)
{
    const float* states = (const float*)d_in[0];
    const float* W1 = (const float*)d_in[1];
    const float* b1 = (const float*)d_in[2];
    const float* W2 = (const float*)d_in[3];
    const float* b2 = (const float*)d_in[4];
    const float* Wm = (const float*)d_in[5];
    const float* bm = (const float*)d_in[6];
    const float* Wc = (const float*)d_in[7];
    const float* bc = (const float*)d_in[8];
    float* out = (float*)d_out;

    const int B = in_sizes[0] / STATE;
    const int ntiles = (B + TILE_M - 1) / TILE_M;
    const size_t smem_bytes = (size_t)F_TOTAL * 4;   // 113152 B

    cudaFuncSetAttribute(actor_mma,
                         cudaFuncAttributeMaxDynamicSharedMemorySize,
                         (int)smem_bytes);

    int grid = ntiles < 304 ? ntiles : 304;          // 2 CTAs x 152 SMs
    actor_mma<<<grid, TPB, smem_bytes>>>(states, W1, b1, W2, b2,
                                         Wm, bm, Wc, bc, out, B);
}

// round 9
// speedup vs baseline: 1.0637x; 1.0637x over previous
#include <cuda_runtime.h>
#include <cuda_fp16.h>
#include <cstdint>

#define TPB     256
#define TILE_M  64
#define STATE   24
#define L1D     100
#define L2D     100
#define NHEAD   27
#define ACT     6

#define NT12    13
#define NT3     4
#define KS1     2
#define KS23    7

#define S1_32   36
#define LO1     16
#define S2_32   116
#define LO2     56

// ---- smem layout (b32 word offsets) ----
#define F_BP1   0
#define F_BP2   (F_BP1 + KS1*NT12*32*4)         //  3328
#define F_BP3   (F_BP2 + KS23*NT12*32*4)        // 14976
#define F_AS1   (F_BP3 + KS23*NT3*32*4)         // 18560  (overlaid: chol f32 64*36)
#define F_AS2   (F_AS1 + TILE_M*S1_32)          // 20864
#define F_MEAN  (F_AS2 + TILE_M*S2_32)          // 28288
#define F_TOTAL (F_MEAN + TILE_M*ACT)           // 28672 words = 114688 B

__constant__ int c_pos[21]   = {0,6,7,12,13,14,18,19,20,21,24,25,26,27,28,30,31,32,33,34,35};
__constant__ int c_upper[15] = {1,2,3,4,5,8,9,10,11,15,16,17,22,23,29};

__device__ __forceinline__ uint32_t packh(__half a, __half b) {
    return (uint32_t)__half_as_ushort(a) | ((uint32_t)__half_as_ushort(b) << 16);
}
__device__ __forceinline__ void split2(float v0, float v1, uint32_t& hi, uint32_t& lo) {
    __half h0 = __float2half_rn(v0), h1 = __float2half_rn(v1);
    __half l0 = __float2half_rn(v0 - __half2float(h0));
    __half l1 = __float2half_rn(v1 - __half2float(h1));
    hi = packh(h0, h1); lo = packh(l0, l1);
}

__device__ __forceinline__ void mma16(float* c, const uint32_t* a, uint32_t b0, uint32_t b1) {
    asm volatile("mma.sync.aligned.m16n8k16.row.col.f32.f16.f16.f32 "
                 "{%0,%1,%2,%3},{%4,%5,%6,%7},{%8,%9},{%0,%1,%2,%3};"
                 : "+f"(c[0]), "+f"(c[1]), "+f"(c[2]), "+f"(c[3])
                 : "r"(a[0]), "r"(a[1]), "r"(a[2]), "r"(a[3]), "r"(b0), "r"(b1));
}

extern __shared__ uint32_t smem[];

// 3-term f16 warp GEMM (R5/R7-proven structure)
template<int KS, int MT, int NTW>
__device__ __forceinline__ void wgemm16(const uint32_t* __restrict__ A32, int S32, int LO,
                                        const uint4* __restrict__ Bp,
                                        int NTT, int nt0, int cnt,
                                        int wrow, int g, int t, int lane,
                                        float (&c)[MT][NTW][4])
{
    #pragma unroll
    for (int mt = 0; mt < MT; mt++)
        #pragma unroll
        for (int j = 0; j < NTW; j++)
            #pragma unroll
            for (int i = 0; i < 4; i++) c[mt][j][i] = 0.0f;

    #pragma unroll 1
    for (int ks = 0; ks < KS; ks++) {
        const int kb = ks * 8 + t;

        uint4 bfr[NTW];
        #pragma unroll
        for (int j = 0; j < NTW; j++)
            if (j < cnt) bfr[j] = Bp[(ks * NTT + nt0 + j) * 32 + lane];

        uint32_t ah[MT][4], al[MT][4];
        #pragma unroll
        for (int mt = 0; mt < MT; mt++) {
            const uint32_t* r0 = A32 + (wrow + 16 * mt + g) * S32;
            const uint32_t* r1 = r0 + 8 * S32;
            ah[mt][0] = r0[kb];          ah[mt][1] = r1[kb];
            ah[mt][2] = r0[kb + 4];      ah[mt][3] = r1[kb + 4];
            al[mt][0] = r0[kb + LO];     al[mt][1] = r1[kb + LO];
            al[mt][2] = r0[kb + LO + 4]; al[mt][3] = r1[kb + LO + 4];
        }

        #pragma unroll
        for (int term = 0; term < 3; term++)
            #pragma unroll
            for (int j = 0; j < NTW; j++) {
                if (j >= cnt) continue;
                uint32_t b0 = (term == 2) ? bfr[j].z : bfr[j].x;
                uint32_t b1 = (term == 2) ? bfr[j].w : bfr[j].y;
                #pragma unroll
                for (int mt = 0; mt < MT; mt++)
                    mma16(c[mt][j], (term == 1) ? al[mt] : ah[mt], b0, b1);
            }
    }
}

template<int MT, int NTW>
__device__ __forceinline__ void epi_relu16(float (&c)[MT][NTW][4], uint32_t* A2,
                                           int wrow, int nt0, int cnt, int g, int t)
{
    #pragma unroll
    for (int mt = 0; mt < MT; mt++) {
        const int row = wrow + 16 * mt + g;
        #pragma unroll
        for (int j = 0; j < NTW; j++) {
            if (j >= cnt) continue;
            const int nt = nt0 + j;
            if (nt == 12 && t >= 2) continue;      // cols >= 100
            const int pi = 4 * nt + t;
            uint32_t h, l;
            split2(fmaxf(c[mt][j][0], 0.f), fmaxf(c[mt][j][1], 0.f), h, l);
            A2[row * S2_32 + pi] = h;  A2[row * S2_32 + LO2 + pi] = l;
            split2(fmaxf(c[mt][j][2], 0.f), fmaxf(c[mt][j][3], 0.f), h, l);
            A2[(row + 8) * S2_32 + pi] = h;  A2[(row + 8) * S2_32 + LO2 + pi] = l;
        }
    }
}

__global__ void __launch_bounds__(TPB, 2)
actor_mma(const float* __restrict__ states,
          const float* __restrict__ W1, const float* __restrict__ b1,
          const float* __restrict__ W2, const float* __restrict__ b2,
          const float* __restrict__ Wm, const float* __restrict__ bm,
          const float* __restrict__ Wc, const float* __restrict__ bc,
          float* __restrict__ out, int B)
{
    const int tid  = threadIdx.x;
    const int lane = tid & 31;
    const int wid  = tid >> 5;
    const int g    = lane >> 2;
    const int t    = lane & 3;

    // layers 1,2 (M=64): M2 x N4
    const int wrow = (wid & 1) * 32;
    const int nh   = wid >> 1;
    const int nt0  = (nh == 0) ? 0 : (1 + 3 * nh);   // {0,4,7,10}
    const int ncnt = (nh == 0) ? 4 : 3;
    // head (M=64, N=32): M4 x N2
    const int wrow3 = (wid & 3) * 16;
    const int nt03  = (wid >> 2) * 2;

    uint32_t* As1 = smem + F_AS1;
    uint32_t* As2 = smem + F_AS2;
    float* sMean  = reinterpret_cast<float*>(smem + F_MEAN);
    float* sChol  = reinterpret_cast<float*>(smem + F_AS1);   // overlay (64*36 words)
    const uint4* Bp1 = reinterpret_cast<const uint4*>(smem + F_BP1);
    const uint4* Bp2 = reinterpret_cast<const uint4*>(smem + F_BP2);
    const uint4* Bp3 = reinterpret_cast<const uint4*>(smem + F_BP3);

    // ---- stage packed f16 hi/lo weight fragments (biases folded as K-column) ----
    for (int i = tid; i < KS1 * NT12 * 32; i += TPB) {
        int ln = i & 31, slot = i >> 5, ks = slot / NT12, nt = slot - ks * NT12;
        int n = (ln >> 2) + 8 * nt, k0 = 16 * ks + 2 * (ln & 3);
        float w[4];
        #pragma unroll
        for (int q = 0; q < 4; q++) {
            int k = k0 + (q >> 1) * 8 + (q & 1);
            w[q] = (n < L1D) ? (k < STATE ? W1[n * STATE + k] : (k == STATE ? b1[n] : 0.f)) : 0.f;
        }
        uint4 fr; uint32_t lo0, lo1;
        split2(w[0], w[1], fr.x, lo0); split2(w[2], w[3], fr.y, lo1);
        fr.z = lo0; fr.w = lo1;
        reinterpret_cast<uint4*>(smem + F_BP1)[i] = fr;
    }
    for (int i = tid; i < KS23 * NT12 * 32; i += TPB) {
        int ln = i & 31, slot = i >> 5, ks = slot / NT12, nt = slot - ks * NT12;
        int n = (ln >> 2) + 8 * nt, k0 = 16 * ks + 2 * (ln & 3);
        float w[4];
        #pragma unroll
        for (int q = 0; q < 4; q++) {
            int k = k0 + (q >> 1) * 8 + (q & 1);
            w[q] = (n < L2D) ? (k < L1D ? W2[n * L1D + k] : (k == L1D ? b2[n] : 0.f)) : 0.f;
        }
        uint4 fr; uint32_t lo0, lo1;
        split2(w[0], w[1], fr.x, lo0); split2(w[2], w[3], fr.y, lo1);
        fr.z = lo0; fr.w = lo1;
        reinterpret_cast<uint4*>(smem + F_BP2)[i] = fr;
    }
    for (int i = tid; i < KS23 * NT3 * 32; i += TPB) {
        int ln = i & 31, slot = i >> 5, ks = slot / NT3, nt = slot - ks * NT3;
        int n = (ln >> 2) + 8 * nt, k0 = 16 * ks + 2 * (ln & 3);
        float w[4];
        #pragma unroll
        for (int q = 0; q < 4; q++) {
            int k = k0 + (q >> 1) * 8 + (q & 1);
            float v = 0.f;
            if (n < ACT)        v = k < L2D ? Wm[n * L2D + k] : (k == L2D ? bm[n] : 0.f);
            else if (n < NHEAD) v = k < L2D ? Wc[(n - ACT) * L2D + k] : (k == L2D ? bc[n - ACT] : 0.f);
            w[q] = v;
        }
        uint4 fr; uint32_t lo0, lo1;
        split2(w[0], w[1], fr.x, lo0); split2(w[2], w[3], fr.y, lo1);
        fr.z = lo0; fr.w = lo1;
        reinterpret_cast<uint4*>(smem + F_BP3)[i] = fr;
    }
    // zero As2, set persistent bias pair 50 (col 100); As1 pads set per-tile
    // (As1 is overlaid by chol staging each tile, so pads must be rewritten in S1)
    for (int i = tid; i < TILE_M * S2_32; i += TPB) As2[i] = 0u;
    __syncthreads();
    if (tid < TILE_M)
        As2[tid * S2_32 + 50] = packh(__float2half_rn(1.f), __ushort_as_half(0));
    __syncthreads();

    const int ntiles = (B + TILE_M - 1) / TILE_M;
    const int grid = gridDim.x;

    // ---- prefetch first tile's X (2 threads per row, 3 float4 each) ----
    float4 px0, px1, px2;
    if (tid < 2 * TILE_M && blockIdx.x < ntiles) {
        long m = (long)blockIdx.x * TILE_M + (tid >> 1); if (m >= B) m = B - 1;
        const float4* src = reinterpret_cast<const float4*>(states + m * STATE) + (tid & 1) * 3;
        px0 = src[0]; px1 = src[1]; px2 = src[2];
    }

    for (int tile = blockIdx.x; tile < ntiles; tile += grid) {
        // ---- write prefetched X into As1 hi/lo planes (+ pads: chol overlay wiped them) ----
        if (tid < 2 * TILE_M) {
            const int row = tid >> 1, half = tid & 1;
            uint32_t* rh = As1 + row * S1_32 + half * 6;
            uint32_t h, l;
            split2(px0.x, px0.y, h, l); rh[0] = h; rh[LO1 + 0] = l;
            split2(px0.z, px0.w, h, l); rh[1] = h; rh[LO1 + 1] = l;
            split2(px1.x, px1.y, h, l); rh[2] = h; rh[LO1 + 2] = l;
            split2(px1.z, px1.w, h, l); rh[3] = h; rh[LO1 + 3] = l;
            split2(px2.x, px2.y, h, l); rh[4] = h; rh[LO1 + 4] = l;
            split2(px2.z, px2.w, h, l); rh[5] = h; rh[LO1 + 5] = l;
            if (half) {
                uint32_t* rr = As1 + row * S1_32;
                rr[12] = packh(__float2half_rn(1.f), __ushort_as_half(0));  // bias col 24
                rr[LO1 + 12] = 0u;
                #pragma unroll
                for (int p = 13; p < 16; p++) { rr[p] = 0u; rr[LO1 + p] = 0u; }
            }
        }
        // ---- prefetch next tile's X ----
        {
            int nxt = tile + grid;
            if (tid < 2 * TILE_M && nxt < ntiles) {
                long m = (long)nxt * TILE_M + (tid >> 1); if (m >= B) m = B - 1;
                const float4* src = reinterpret_cast<const float4*>(states + m * STATE) + (tid & 1) * 3;
                px0 = src[0]; px1 = src[1]; px2 = src[2];
            }
        }
        __syncthreads();                                   // S1: X ready

        // ---- layer 1: As1 -> As2 ----
        {
            float c1[2][4][4];
            wgemm16<KS1, 2, 4>(As1, S1_32, LO1, Bp1, NT12, nt0, ncnt, wrow, g, t, lane, c1);
            epi_relu16<2, 4>(c1, As2, wrow, nt0, ncnt, g, t);
        }
        __syncthreads();                                   // S2: hidden1 ready

        // ---- layer 2: As2 -> As2 (named barrier per 128-thread m-group) ----
        {
            float c2[2][4][4];
            wgemm16<KS23, 2, 4>(As2, S2_32, LO2, Bp2, NT12, nt0, ncnt, wrow, g, t, lane, c2);
            asm volatile("bar.sync %0, %1;" :: "r"(1 + (wid & 1)), "r"(128) : "memory");
            epi_relu16<2, 4>(c2, As2, wrow, nt0, ncnt, g, t);
        }
        __syncthreads();                                   // S4: hidden2 ready

        // ---- head gemm + staged activation scatter ----
        {
            float c3[1][2][4];
            wgemm16<KS23, 1, 2>(As2, S2_32, LO2, Bp3, NT3, nt03, 2, wrow3, g, t, lane, c3);
            #pragma unroll
            for (int j = 0; j < 2; j++)
                #pragma unroll
                for (int i = 0; i < 4; i++) {
                    int row = wrow3 + g + ((i >= 2) ? 8 : 0);
                    int col = 8 * (nt03 + j) + 2 * t + (i & 1);
                    float v = c3[0][j][i];
                    if (col < ACT) {
                        sMean[row * ACT + col] = tanhf(v);
                    } else if (col < NHEAD) {
                        float sp = fmaxf(v, 0.f) + log1pf(expf(-fabsf(v)));
                        sChol[row * 36 + c_pos[col - ACT]] = sp;
                    }
                }
            if (tid < TILE_M) {
                #pragma unroll
                for (int j = 0; j < 15; j++) sChol[tid * 36 + c_upper[j]] = 0.0f;
            }
        }
        __syncthreads();                                   // S5: staged

        // ---- coalesced writeback ----
        if ((tile + 1) * TILE_M <= B) {
            float4* pm = reinterpret_cast<float4*>(out + (size_t)tile * (TILE_M * ACT));
            const float4* sm4 = reinterpret_cast<const float4*>(sMean);
            for (int i = tid; i < TILE_M * ACT / 4; i += TPB) pm[i] = sm4[i];
            float4* pc = reinterpret_cast<float4*>(out + (size_t)B * ACT + (size_t)tile * (TILE_M * 36));
            const float4* sc4 = reinterpret_cast<const float4*>(sChol);
            for (int i = tid; i < TILE_M * 36 / 4; i += TPB) pc[i] = sc4[i];
        } else {
            int nrow = B - tile * TILE_M;
            for (int i = tid; i < nrow * ACT; i += TPB)
                out[(size_t)tile * (TILE_M * ACT) + i] = sMean[i];
            for (int i = tid; i < nrow * 36; i += TPB)
                out[(size_t)B * ACT + (size_t)tile * (TILE_M * 36) + i] = sChol[i];
        }
        __syncthreads();                                   // S6: As1 overlay free
    }
}

extern "C" void kernel_launch(void* const* d_in, const int* in_sizes, int n_in,
                              void* d_out, int out_size)
{
    const float* states = (const float*)d_in[0];
    const float* W1 = (const float*)d_in[1];
    const float* b1 = (const float*)d_in[2];
    const float* W2 = (const float*)d_in[3];
    const float* b2 = (const float*)d_in[4];
    const float* Wm = (const float*)d_in[5];
    const float* bm = (const float*)d_in[6];
    const float* Wc = (const float*)d_in[7];
    const float* bc = (const float*)d_in[8];
    float* out = (float*)d_out;

    const int B = in_sizes[0] / STATE;
    const int ntiles = (B + TILE_M - 1) / TILE_M;
    const size_t smem_bytes = (size_t)F_TOTAL * 4;   // 114688 B = 112 KB

    cudaFuncSetAttribute(actor_mma,
                         cudaFuncAttributeMaxDynamicSharedMemorySize,
                         (int)smem_bytes);

    int grid = ntiles < 304 ? ntiles : 304;          // 2 CTAs x 152 SMs
    actor_mma<<<grid, TPB, smem_bytes>>>(states, W1, b1, W2, b2,
                                         Wm, bm, Wc, bc, out, B);
}

// round 10
// speedup vs baseline: 1.2064x; 1.1341x over previous
#include <cuda_runtime.h>
#include <cuda_fp16.h>
#include <cstdint>

#define TPB     512
#define TILE_M  32
#define STATE   24
#define L1D     100
#define L2D     100
#define NHEAD   27
#define ACT     6

#define NT12    13
#define NT3     4
#define KS1     2
#define KS23    7

#define S1_32   36
#define LO1     16
#define S2_32   116
#define LO2     56

// ---- smem layout (b32 word offsets) ----
#define F_BP1   0
#define F_BP2   (F_BP1 + KS1*NT12*32*4)         //  3328
#define F_BP3   (F_BP2 + KS23*NT12*32*4)        // 14976
#define F_PIPE  (F_BP3 + KS23*NT3*32*4)         // 18560
// per-pipeline block (words): As1 | As2 | chol stage | mean stage
#define P_AS1   0
#define P_AS2   (TILE_M*S1_32)                  // 1152
#define P_CHOL  (P_AS2 + TILE_M*S2_32)          // 4864
#define P_MEAN  (P_CHOL + TILE_M*36)            // 6016
#define PIPE_W  (P_MEAN + TILE_M*ACT)           // 6208 words
#define F_TOTAL (F_PIPE + 4*PIPE_W)             // 43392 words = 173568 B

__constant__ int c_pos[21]   = {0,6,7,12,13,14,18,19,20,21,24,25,26,27,28,30,31,32,33,34,35};
__constant__ int c_upper[15] = {1,2,3,4,5,8,9,10,11,15,16,17,22,23,29};

__device__ __forceinline__ uint32_t packh(__half a, __half b) {
    return (uint32_t)__half_as_ushort(a) | ((uint32_t)__half_as_ushort(b) << 16);
}
__device__ __forceinline__ void split2(float v0, float v1, uint32_t& hi, uint32_t& lo) {
    __half h0 = __float2half_rn(v0), h1 = __float2half_rn(v1);
    __half l0 = __float2half_rn(v0 - __half2float(h0));
    __half l1 = __float2half_rn(v1 - __half2float(h1));
    hi = packh(h0, h1); lo = packh(l0, l1);
}

__device__ __forceinline__ void mma16(float* c, const uint32_t* a, uint32_t b0, uint32_t b1) {
    asm volatile("mma.sync.aligned.m16n8k16.row.col.f32.f16.f16.f32 "
                 "{%0,%1,%2,%3},{%4,%5,%6,%7},{%8,%9},{%0,%1,%2,%3};"
                 : "+f"(c[0]), "+f"(c[1]), "+f"(c[2]), "+f"(c[3])
                 : "r"(a[0]), "r"(a[1]), "r"(a[2]), "r"(a[3]), "r"(b0), "r"(b1));
}

#define PIPE_BAR() asm volatile("bar.sync %0, 128;" :: "r"(1 + pipe) : "memory")

extern __shared__ uint32_t smem[];

// 3-term f16 warp GEMM (proven structure; MT=1 here)
template<int KS, int MT, int NTW>
__device__ __forceinline__ void wgemm16(const uint32_t* __restrict__ A32, int S32, int LO,
                                        const uint4* __restrict__ Bp,
                                        int NTT, int nt0, int cnt,
                                        int wrow, int g, int t, int lane,
                                        float (&c)[MT][NTW][4])
{
    #pragma unroll
    for (int mt = 0; mt < MT; mt++)
        #pragma unroll
        for (int j = 0; j < NTW; j++)
            #pragma unroll
            for (int i = 0; i < 4; i++) c[mt][j][i] = 0.0f;

    #pragma unroll 1
    for (int ks = 0; ks < KS; ks++) {
        const int kb = ks * 8 + t;

        uint4 bfr[NTW];
        #pragma unroll
        for (int j = 0; j < NTW; j++)
            if (j < cnt) bfr[j] = Bp[(ks * NTT + nt0 + j) * 32 + lane];

        uint32_t ah[MT][4], al[MT][4];
        #pragma unroll
        for (int mt = 0; mt < MT; mt++) {
            const uint32_t* r0 = A32 + (wrow + 16 * mt + g) * S32;
            const uint32_t* r1 = r0 + 8 * S32;
            ah[mt][0] = r0[kb];          ah[mt][1] = r1[kb];
            ah[mt][2] = r0[kb + 4];      ah[mt][3] = r1[kb + 4];
            al[mt][0] = r0[kb + LO];     al[mt][1] = r1[kb + LO];
            al[mt][2] = r0[kb + LO + 4]; al[mt][3] = r1[kb + LO + 4];
        }

        #pragma unroll
        for (int term = 0; term < 3; term++)
            #pragma unroll
            for (int j = 0; j < NTW; j++) {
                if (j >= cnt) continue;
                uint32_t b0 = (term == 2) ? bfr[j].z : bfr[j].x;
                uint32_t b1 = (term == 2) ? bfr[j].w : bfr[j].y;
                #pragma unroll
                for (int mt = 0; mt < MT; mt++)
                    mma16(c[mt][j], (term == 1) ? al[mt] : ah[mt], b0, b1);
            }
    }
}

template<int MT, int NTW>
__device__ __forceinline__ void epi_relu16(float (&c)[MT][NTW][4], uint32_t* A2,
                                           int wrow, int nt0, int cnt, int g, int t)
{
    #pragma unroll
    for (int mt = 0; mt < MT; mt++) {
        const int row = wrow + 16 * mt + g;
        #pragma unroll
        for (int j = 0; j < NTW; j++) {
            if (j >= cnt) continue;
            const int nt = nt0 + j;
            if (nt == 12 && t >= 2) continue;      // cols >= 100
            const int pi = 4 * nt + t;
            uint32_t h, l;
            split2(fmaxf(c[mt][j][0], 0.f), fmaxf(c[mt][j][1], 0.f), h, l);
            A2[row * S2_32 + pi] = h;  A2[row * S2_32 + LO2 + pi] = l;
            split2(fmaxf(c[mt][j][2], 0.f), fmaxf(c[mt][j][3], 0.f), h, l);
            A2[(row + 8) * S2_32 + pi] = h;  A2[(row + 8) * S2_32 + LO2 + pi] = l;
        }
    }
}

__global__ void __launch_bounds__(TPB, 1)
actor_mma(const float* __restrict__ states,
          const float* __restrict__ W1, const float* __restrict__ b1,
          const float* __restrict__ W2, const float* __restrict__ b2,
          const float* __restrict__ Wm, const float* __restrict__ bm,
          const float* __restrict__ Wc, const float* __restrict__ bc,
          float* __restrict__ out, int B)
{
    const int tid  = threadIdx.x;
    const int lane = tid & 31;
    const int wid  = tid >> 5;
    const int g    = lane >> 2;
    const int t    = lane & 3;

    const int pipe = wid >> 2;        // 0..3 — one warp per SMSP per pipeline
    const int w    = wid & 3;         // warp within pipeline
    const int ptid = tid & 127;       // thread within pipeline

    // layers 1,2 (M=32): M2 x N2 -> warp: 16 rows, 7-or-6 n-tiles
    const int wrow = (w & 1) * 16;
    const int nt0  = (w >> 1) * 7;                 // {0, 7}
    const int ncnt = (w >> 1) ? 6 : 7;
    // head (M=32, N=32): M2 x N2
    const int wrow3 = (w & 1) * 16;
    const int nt03  = (w >> 1) * 2;

    uint32_t* pb   = smem + F_PIPE + pipe * PIPE_W;
    uint32_t* As1  = pb + P_AS1;
    uint32_t* As2  = pb + P_AS2;
    float* sChol   = reinterpret_cast<float*>(pb + P_CHOL);
    float* sMean   = reinterpret_cast<float*>(pb + P_MEAN);
    const uint4* Bp1 = reinterpret_cast<const uint4*>(smem + F_BP1);
    const uint4* Bp2 = reinterpret_cast<const uint4*>(smem + F_BP2);
    const uint4* Bp3 = reinterpret_cast<const uint4*>(smem + F_BP3);

    // ---- stage packed f16 hi/lo weight fragments (biases folded as K-column) ----
    for (int i = tid; i < KS1 * NT12 * 32; i += TPB) {
        int ln = i & 31, slot = i >> 5, ks = slot / NT12, nt = slot - ks * NT12;
        int n = (ln >> 2) + 8 * nt, k0 = 16 * ks + 2 * (ln & 3);
        float wv[4];
        #pragma unroll
        for (int q = 0; q < 4; q++) {
            int k = k0 + (q >> 1) * 8 + (q & 1);
            wv[q] = (n < L1D) ? (k < STATE ? W1[n * STATE + k] : (k == STATE ? b1[n] : 0.f)) : 0.f;
        }
        uint4 fr; uint32_t lo0, lo1;
        split2(wv[0], wv[1], fr.x, lo0); split2(wv[2], wv[3], fr.y, lo1);
        fr.z = lo0; fr.w = lo1;
        reinterpret_cast<uint4*>(smem + F_BP1)[i] = fr;
    }
    for (int i = tid; i < KS23 * NT12 * 32; i += TPB) {
        int ln = i & 31, slot = i >> 5, ks = slot / NT12, nt = slot - ks * NT12;
        int n = (ln >> 2) + 8 * nt, k0 = 16 * ks + 2 * (ln & 3);
        float wv[4];
        #pragma unroll
        for (int q = 0; q < 4; q++) {
            int k = k0 + (q >> 1) * 8 + (q & 1);
            wv[q] = (n < L2D) ? (k < L1D ? W2[n * L1D + k] : (k == L1D ? b2[n] : 0.f)) : 0.f;
        }
        uint4 fr; uint32_t lo0, lo1;
        split2(wv[0], wv[1], fr.x, lo0); split2(wv[2], wv[3], fr.y, lo1);
        fr.z = lo0; fr.w = lo1;
        reinterpret_cast<uint4*>(smem + F_BP2)[i] = fr;
    }
    for (int i = tid; i < KS23 * NT3 * 32; i += TPB) {
        int ln = i & 31, slot = i >> 5, ks = slot / NT3, nt = slot - ks * NT3;
        int n = (ln >> 2) + 8 * nt, k0 = 16 * ks + 2 * (ln & 3);
        float wv[4];
        #pragma unroll
        for (int q = 0; q < 4; q++) {
            int k = k0 + (q >> 1) * 8 + (q & 1);
            float v = 0.f;
            if (n < ACT)        v = k < L2D ? Wm[n * L2D + k] : (k == L2D ? bm[n] : 0.f);
            else if (n < NHEAD) v = k < L2D ? Wc[(n - ACT) * L2D + k] : (k == L2D ? bc[n - ACT] : 0.f);
            wv[q] = v;
        }
        uint4 fr; uint32_t lo0, lo1;
        split2(wv[0], wv[1], fr.x, lo0); split2(wv[2], wv[3], fr.y, lo1);
        fr.z = lo0; fr.w = lo1;
        reinterpret_cast<uint4*>(smem + F_BP3)[i] = fr;
    }
    // one-time per-pipeline activation pad init (no overlays -> persistent)
    for (int i = ptid; i < TILE_M * S2_32; i += 128) As2[i] = 0u;
    __syncthreads();
    if (ptid < TILE_M) {
        const uint32_t one = packh(__float2half_rn(1.f), __ushort_as_half(0));
        As2[ptid * S2_32 + 50] = one;                 // bias col 100
        uint32_t* rr = As1 + ptid * S1_32;
        rr[12] = one;  rr[LO1 + 12] = 0u;             // bias col 24
        #pragma unroll
        for (int p = 13; p < 16; p++) { rr[p] = 0u; rr[LO1 + p] = 0u; }
    }
    __syncthreads();

    const int ntiles = (B + TILE_M - 1) / TILE_M;
    const int stride = gridDim.x * 4;
    const int tile0  = blockIdx.x * 4 + pipe;

    // ---- prefetch first tile's X (4 threads per row, one float4+pair each... 
    //      simpler: 2 threads/row over 32 rows = 64 threads, 3 float4 each) ----
    float4 px0, px1, px2;
    if (ptid < 2 * TILE_M && tile0 < ntiles) {
        long m = (long)tile0 * TILE_M + (ptid >> 1); if (m >= B) m = B - 1;
        const float4* src = reinterpret_cast<const float4*>(states + m * STATE) + (ptid & 1) * 3;
        px0 = src[0]; px1 = src[1]; px2 = src[2];
    }

    for (int tile = tile0; tile < ntiles; tile += stride) {
        // ---- write prefetched X into As1 hi/lo planes ----
        if (ptid < 2 * TILE_M) {
            const int row = ptid >> 1, half = ptid & 1;
            uint32_t* rh = As1 + row * S1_32 + half * 6;
            uint32_t h, l;
            split2(px0.x, px0.y, h, l); rh[0] = h; rh[LO1 + 0] = l;
            split2(px0.z, px0.w, h, l); rh[1] = h; rh[LO1 + 1] = l;
            split2(px1.x, px1.y, h, l); rh[2] = h; rh[LO1 + 2] = l;
            split2(px1.z, px1.w, h, l); rh[3] = h; rh[LO1 + 3] = l;
            split2(px2.x, px2.y, h, l); rh[4] = h; rh[LO1 + 4] = l;
            split2(px2.z, px2.w, h, l); rh[5] = h; rh[LO1 + 5] = l;
        }
        // ---- prefetch next tile's X ----
        {
            int nxt = tile + stride;
            if (ptid < 2 * TILE_M && nxt < ntiles) {
                long m = (long)nxt * TILE_M + (ptid >> 1); if (m >= B) m = B - 1;
                const float4* src = reinterpret_cast<const float4*>(states + m * STATE) + (ptid & 1) * 3;
                px0 = src[0]; px1 = src[1]; px2 = src[2];
            }
        }
        PIPE_BAR();                                        // S1: X ready

        // ---- layer 1: As1 -> As2 ----
        {
            float c1[1][7][4];
            wgemm16<KS1, 1, 7>(As1, S1_32, LO1, Bp1, NT12, nt0, ncnt, wrow, g, t, lane, c1);
            epi_relu16<1, 7>(c1, As2, wrow, nt0, ncnt, g, t);
        }
        PIPE_BAR();                                        // S2: hidden1 ready

        // ---- layer 2: As2 -> As2 ----
        {
            float c2[1][7][4];
            wgemm16<KS23, 1, 7>(As2, S2_32, LO2, Bp2, NT12, nt0, ncnt, wrow, g, t, lane, c2);
            PIPE_BAR();                                    // S3: reads done
            epi_relu16<1, 7>(c2, As2, wrow, nt0, ncnt, g, t);
        }
        PIPE_BAR();                                        // S4: hidden2 ready

        // ---- head gemm + staged activation scatter ----
        {
            float c3[1][2][4];
            wgemm16<KS23, 1, 2>(As2, S2_32, LO2, Bp3, NT3, nt03, 2, wrow3, g, t, lane, c3);
            #pragma unroll
            for (int j = 0; j < 2; j++)
                #pragma unroll
                for (int i = 0; i < 4; i++) {
                    int row = wrow3 + g + ((i >= 2) ? 8 : 0);
                    int col = 8 * (nt03 + j) + 2 * t + (i & 1);
                    float v = c3[0][j][i];
                    if (col < ACT) {
                        sMean[row * ACT + col] = tanhf(v);
                    } else if (col < NHEAD) {
                        float sp = fmaxf(v, 0.f) + log1pf(expf(-fabsf(v)));
                        sChol[row * 36 + c_pos[col - ACT]] = sp;
                    }
                }
            if (ptid < TILE_M) {
                #pragma unroll
                for (int j = 0; j < 15; j++) sChol[ptid * 36 + c_upper[j]] = 0.0f;
            }
        }
        PIPE_BAR();                                        // S5: staged

        // ---- coalesced writeback (128 threads of this pipeline) ----
        if ((tile + 1) * TILE_M <= B) {
            float4* pm = reinterpret_cast<float4*>(out + (size_t)tile * (TILE_M * ACT));
            const float4* sm4 = reinterpret_cast<const float4*>(sMean);
            for (int i = ptid; i < TILE_M * ACT / 4; i += 128) pm[i] = sm4[i];
            float4* pc = reinterpret_cast<float4*>(out + (size_t)B * ACT + (size_t)tile * (TILE_M * 36));
            const float4* sc4 = reinterpret_cast<const float4*>(sChol);
            for (int i = ptid; i < TILE_M * 36 / 4; i += 128) pc[i] = sc4[i];
        } else {
            int nrow = B - tile * TILE_M;
            for (int i = ptid; i < nrow * ACT; i += 128)
                out[(size_t)tile * (TILE_M * ACT) + i] = sMean[i];
            for (int i = ptid; i < nrow * 36; i += 128)
                out[(size_t)B * ACT + (size_t)tile * (TILE_M * 36) + i] = sChol[i];
        }
        PIPE_BAR();                                        // S6: stage free
    }
}

extern "C" void kernel_launch(void* const* d_in, const int* in_sizes, int n_in,
                              void* d_out, int out_size)
{
    const float* states = (const float*)d_in[0];
    const float* W1 = (const float*)d_in[1];
    const float* b1 = (const float*)d_in[2];
    const float* W2 = (const float*)d_in[3];
    const float* b2 = (const float*)d_in[4];
    const float* Wm = (const float*)d_in[5];
    const float* bm = (const float*)d_in[6];
    const float* Wc = (const float*)d_in[7];
    const float* bc = (const float*)d_in[8];
    float* out = (float*)d_out;

    const int B = in_sizes[0] / STATE;
    const int ntiles = (B + TILE_M - 1) / TILE_M;
    const size_t smem_bytes = (size_t)F_TOTAL * 4;   // 173568 B

    cudaFuncSetAttribute(actor_mma,
                         cudaFuncAttributeMaxDynamicSharedMemorySize,
                         (int)smem_bytes);

    int nstreams = (ntiles + 3) / 4;
    int grid = nstreams < 152 ? nstreams : 152;      // 1 CTA/SM, 4 pipelines each
    actor_mma<<<grid, TPB, smem_bytes>>>(states, W1, b1, W2, b2,
                                         Wm, bm, Wc, bc, out, B);
}